// round 2
// baseline (speedup 1.0000x reference)
#include <cuda_runtime.h>
#include <cuda_bf16.h>
#include <cstdint>

// Problem constants
#define NV     6000          // vertices (batch M)
#define RR     5             // radial
#define AA     8             // angular (= n_rotations)
#define FF     128           // features
#define KK     2             // kernel "K" dim
#define OO     128           // output channels
#define RA     40            // R*A
#define KDIM   5120          // RA*FF  (GEMM K)
#define NOUT   2048          // 8 rot * KK * OO (GEMM N)

// Scratch (device globals — no allocations allowed)
__device__ float g_sig[(size_t)NV * RA * FF];      // (N, q, f)  122.9 MB
__device__ float g_Wc [(size_t)NOUT * KDIM];       // (j, t) = B^T layout, 41.9 MB
__device__ float g_S  [(size_t)NV * NOUT];         // GEMM result, 49.2 MB

// ---------------------------------------------------------------------------
// Kernel 1: gather + barycentric interpolation
//   sig[row=n*40+q][f] = sum_j w_j * mesh_signal[idx_j][f]
// ---------------------------------------------------------------------------
__global__ void gather_bary(const float* __restrict__ ms,
                            const float* __restrict__ bary)
{
    const int row = blockIdx.x;          // 0 .. N*RA-1
    const int f   = threadIdx.x;         // 0 .. 127
    const float* b = bary + (size_t)row * 6;   // (3 verts)x(idx,w)
    const int   i0 = (int)b[0];  const float w0 = b[1];
    const int   i1 = (int)b[2];  const float w1 = b[3];
    const int   i2 = (int)b[4];  const float w2 = b[5];
    float v = w0 * __ldg(&ms[(size_t)i0 * FF + f])
            + w1 * __ldg(&ms[(size_t)i1 * FF + f])
            + w2 * __ldg(&ms[(size_t)i2 * FF + f]);
    g_sig[(size_t)row * FF + f] = v;
}

// ---------------------------------------------------------------------------
// Kernel 2: fold interp-coeffs + rotation into the GEMM weights.
//   Wc[j = rot*256 + k*128 + o][t = q*128 + f]
//      = sum_{r,b} interp[r,b,q] * W[r,(b+rot)%8,k,o,f]
// One block per j; block caches the 40 (r,a) weight rows for (k,o) in smem.
// ---------------------------------------------------------------------------
__global__ void build_wc(const float* __restrict__ W,
                         const float* __restrict__ interp)
{
    const int j   = blockIdx.x;           // 0..2047
    const int rot = j >> 8;
    const int k   = (j >> 7) & 1;
    const int o   = j & 127;
    const int f   = threadIdx.x;          // 0..127

    __shared__ float s_w[RA][FF];         // 20 KB
    __shared__ float s_c[RA][RA];         // 6.4 KB

    for (int ra = 0; ra < RA; ra++)
        s_w[ra][f] = W[(((size_t)ra * KK + k) * OO + o) * FF + f];
    for (int i = f; i < RA * RA; i += FF)
        s_c[i / RA][i % RA] = interp[i];
    __syncthreads();

    for (int q = 0; q < RA; q++) {
        float acc = 0.f;
        #pragma unroll
        for (int r = 0; r < RR; r++) {
            #pragma unroll
            for (int b = 0; b < AA; b++) {
                const int ap = (b + rot) & 7;
                acc += s_c[r * AA + b][q] * s_w[r * AA + ap][f];
            }
        }
        g_Wc[(size_t)j * KDIM + q * FF + f] = acc;
    }
}

// ---------------------------------------------------------------------------
// Kernel 3: GEMM  S[n][j] = sum_t sig[n][t] * Wc[j][t]
//   A: row-major (NV x KDIM), B^T: row-major (NOUT x KDIM)  -> "NT" gemm
//   Tiles: BM=128, BN=64, BK=16, 256 threads, 8x4 per-thread micro-tile.
// ---------------------------------------------------------------------------
#define BM 128
#define BN 64
#define BK 16

__global__ __launch_bounds__(256) void gemm_nt()
{
    const int tid = threadIdx.x;
    const int n0  = blockIdx.x * BN;     // 32 tiles
    const int m0  = blockIdx.y * BM;     // 47 tiles (last partial)

    __shared__ float As[BK][BM];         // 8 KB  (k-major for frag loads)
    __shared__ float Bs[BK][BN];         // 4 KB

    const int tx = tid & 15;             // 0..15 -> 4 cols each
    const int ty = tid >> 4;             // 0..15 -> 8 rows each

    float acc[8][4];
    #pragma unroll
    for (int i = 0; i < 8; i++)
        #pragma unroll
        for (int jj = 0; jj < 4; jj++) acc[i][jj] = 0.f;

    const int aRow  = tid >> 2;          // 0..63 (then +64)
    const int aCol4 = tid & 3;           // which float4 in the 16-wide k slab
    const int bRow  = tid >> 2;          // 0..63
    const int bCol4 = tid & 3;

    for (int k0 = 0; k0 < KDIM; k0 += BK) {
        // load A tile (128 x 16), transposed into As[k][m]
        #pragma unroll
        for (int half = 0; half < 2; half++) {
            const int r = aRow + half * 64;
            const int gm = m0 + r;
            float4 av = make_float4(0.f, 0.f, 0.f, 0.f);
            if (gm < NV)
                av = *(const float4*)&g_sig[(size_t)gm * KDIM + k0 + aCol4 * 4];
            As[aCol4 * 4 + 0][r] = av.x;
            As[aCol4 * 4 + 1][r] = av.y;
            As[aCol4 * 4 + 2][r] = av.z;
            As[aCol4 * 4 + 3][r] = av.w;
        }
        // load B tile (64 x 16), transposed into Bs[k][j]
        {
            const int gj = n0 + bRow;
            float4 bv = *(const float4*)&g_Wc[(size_t)gj * KDIM + k0 + bCol4 * 4];
            Bs[bCol4 * 4 + 0][bRow] = bv.x;
            Bs[bCol4 * 4 + 1][bRow] = bv.y;
            Bs[bCol4 * 4 + 2][bRow] = bv.z;
            Bs[bCol4 * 4 + 3][bRow] = bv.w;
        }
        __syncthreads();

        #pragma unroll
        for (int kk = 0; kk < BK; kk++) {
            float a[8], bb[4];
            *(float4*)&a[0] = *(const float4*)&As[kk][ty * 8];
            *(float4*)&a[4] = *(const float4*)&As[kk][ty * 8 + 4];
            *(float4*)&bb[0] = *(const float4*)&Bs[kk][tx * 4];
            #pragma unroll
            for (int i = 0; i < 8; i++)
                #pragma unroll
                for (int jj = 0; jj < 4; jj++)
                    acc[i][jj] = fmaf(a[i], bb[jj], acc[i][jj]);
        }
        __syncthreads();
    }

    #pragma unroll
    for (int i = 0; i < 8; i++) {
        const int gm = m0 + ty * 8 + i;
        if (gm < NV) {
            float4 v = make_float4(acc[i][0], acc[i][1], acc[i][2], acc[i][3]);
            *(float4*)&g_S[(size_t)gm * NOUT + n0 + tx * 4] = v;
        }
    }
}

// ---------------------------------------------------------------------------
// Kernel 4: epilogue  out[n,rot,o] = relu(s_k0 + 40*b0) + relu(s_k1 + 40*b1)
// ---------------------------------------------------------------------------
__global__ void epilogue(const float* __restrict__ bias, float* __restrict__ out)
{
    const int idx = blockIdx.x * 256 + threadIdx.x;   // over N*8*128
    if (idx >= NV * AA * OO) return;
    const int o   = idx & 127;
    const int rot = (idx >> 7) & 7;
    const int n   = idx >> 10;
    const float b0 = 40.f * __ldg(&bias[o]);
    const float b1 = 40.f * __ldg(&bias[OO + o]);
    const float* Srow = g_S + (size_t)n * NOUT + rot * (KK * OO);
    const float s0 = Srow[o] + b0;
    const float s1 = Srow[OO + o] + b1;
    out[idx] = fmaxf(s0, 0.f) + fmaxf(s1, 0.f);
}

// ---------------------------------------------------------------------------
extern "C" void kernel_launch(void* const* d_in, const int* in_sizes, int n_in,
                              void* d_out, int out_size)
{
    const float *ms = nullptr, *bary = nullptr, *W = nullptr,
                *bias = nullptr, *interp = nullptr;
    for (int i = 0; i < n_in; i++) {
        switch (in_sizes[i]) {
            case NV * FF:                 ms     = (const float*)d_in[i]; break; // 768000
            case NV * RA * 3:             bary   = (const float*)d_in[i]; break; // 720000 (x2 last dim folded? no)
            case NV * RA * 3 * 2:         bary   = (const float*)d_in[i]; break; // 1440000
            case RA * KK * OO * FF:       W      = (const float*)d_in[i]; break; // 1310720
            case KK * OO:                 bias   = (const float*)d_in[i]; break; // 256
            case RA * RA:                 interp = (const float*)d_in[i]; break; // 1600
            default: break;
        }
    }
    float* out = (float*)d_out;

    gather_bary<<<NV * RA, FF>>>(ms, bary);
    build_wc<<<NOUT, FF>>>(W, interp);
    dim3 gg(NOUT / BN, (NV + BM - 1) / BM);
    gemm_nt<<<gg, 256>>>();
    epilogue<<<(NV * AA * OO + 255) / 256, 256>>>(bias, out);
}

// round 4
// speedup vs baseline: 1.8379x; 1.8379x over previous
#include <cuda_runtime.h>
#include <cuda_bf16.h>
#include <cstdint>

// ---------------- problem constants ----------------
#define NV    6000
#define RR    5
#define AA    8
#define FF    128
#define KK    2
#define OO    128
#define RA    40
#define KDIM  5120
#define NROT  8
#define NOUTJ (NROT*KK*OO)        // 2048 GEMM columns

// ---------------- GEMM tiling ----------------
#define BM    128
#define BN    256                 // = one rot (KK*OO)
#define BK    32                  // bf16 per k-stage
#define NSEG  3                   // ah*bh, al*bh, ah*bl
#define CPS   (KDIM/BK)           // 160 chunks per segment
#define NS    (NSEG*CPS)          // 480 stages
#define AST   40                  // padded smem row stride (bf16): 80B, conflict-free
#define A_BYTES (BM*AST*2)        // 10240
#define B_BYTES (BN*AST*2)        // 20480
#define STG_BYTES (A_BYTES + B_BYTES)   // 30720
#define NSTG  4
#define DYNSMEM (NSTG*STG_BYTES)  // 122880  (epilogue 128x132 f32 = 67.6KB reuses this)

// ---------------- scratch (device globals; no allocs allowed) ----------------
__device__ __nv_bfloat16 g_Ah[(size_t)NV * KDIM];
__device__ __nv_bfloat16 g_Al[(size_t)NV * KDIM];
__device__ __nv_bfloat16 g_Bh[(size_t)NOUTJ * KDIM];
__device__ __nv_bfloat16 g_Bl[(size_t)NOUTJ * KDIM];

// ---------------- PTX helpers (base sm_103 features only) ----------------
__device__ __forceinline__ uint32_t smem_u32(const void* p) {
    uint32_t a;
    asm("{ .reg .u64 t; cvta.to.shared.u64 t, %1; cvt.u32.u64 %0, t; }"
        : "=r"(a) : "l"(p));
    return a;
}

__device__ __forceinline__ void cpasync16(uint32_t saddr, const void* g, int srcsz) {
    asm volatile("cp.async.cg.shared.global [%0], [%1], 16, %2;"
                 :: "r"(saddr), "l"(g), "r"(srcsz) : "memory");
}
#define CP_COMMIT() asm volatile("cp.async.commit_group;" ::: "memory")
#define CP_WAIT2()  asm volatile("cp.async.wait_group 2;" ::: "memory")

__device__ __forceinline__ void ldsm_x4(uint32_t* r, uint32_t addr) {
    asm volatile("ldmatrix.sync.aligned.m8n8.x4.shared.b16 {%0,%1,%2,%3}, [%4];"
                 : "=r"(r[0]), "=r"(r[1]), "=r"(r[2]), "=r"(r[3]) : "r"(addr));
}

__device__ __forceinline__ void mma_bf16(float* d, const uint32_t* a, const uint32_t* b) {
    asm volatile(
        "mma.sync.aligned.m16n8k16.row.col.f32.bf16.bf16.f32 "
        "{%0,%1,%2,%3}, {%4,%5,%6,%7}, {%8,%9}, {%0,%1,%2,%3};"
        : "+f"(d[0]), "+f"(d[1]), "+f"(d[2]), "+f"(d[3])
        : "r"(a[0]), "r"(a[1]), "r"(a[2]), "r"(a[3]), "r"(b[0]), "r"(b[1]));
}

// ---------------------------------------------------------------------------
// Kernel 1: gather + barycentric -> bf16 hi/lo A
// ---------------------------------------------------------------------------
__global__ void gather_bary(const float* __restrict__ ms,
                            const float* __restrict__ bary)
{
    const int row = blockIdx.x;          // n*RA + q
    const int f   = threadIdx.x;
    const float* b = bary + (size_t)row * 6;
    const int   i0 = (int)b[0];  const float w0 = b[1];
    const int   i1 = (int)b[2];  const float w1 = b[3];
    const int   i2 = (int)b[4];  const float w2 = b[5];
    float v = w0 * __ldg(&ms[(size_t)i0 * FF + f])
            + w1 * __ldg(&ms[(size_t)i1 * FF + f])
            + w2 * __ldg(&ms[(size_t)i2 * FF + f]);
    __nv_bfloat16 h = __float2bfloat16(v);
    const size_t idx = (size_t)row * FF + f;    // == n*KDIM + q*FF + f
    g_Ah[idx] = h;
    g_Al[idx] = __float2bfloat16(v - __bfloat162float(h));
}

// ---------------------------------------------------------------------------
// Kernel 2: fold interp + rotation into weights -> bf16 hi/lo B (N x K)
// ---------------------------------------------------------------------------
__global__ void build_wc(const float* __restrict__ W,
                         const float* __restrict__ interp)
{
    const int j   = blockIdx.x;
    const int rot = j >> 8;
    const int k   = (j >> 7) & 1;
    const int o   = j & 127;
    const int f   = threadIdx.x;

    __shared__ float s_w[RA][FF];
    __shared__ float s_c[RA][RA];

    for (int ra = 0; ra < RA; ra++)
        s_w[ra][f] = W[(((size_t)ra * KK + k) * OO + o) * FF + f];
    for (int i = f; i < RA * RA; i += FF)
        s_c[i / RA][i % RA] = interp[i];
    __syncthreads();

    for (int q = 0; q < RA; q++) {
        float acc = 0.f;
        #pragma unroll
        for (int r = 0; r < RR; r++)
            #pragma unroll
            for (int b = 0; b < AA; b++)
                acc += s_c[r * AA + b][q] * s_w[r * AA + ((b + rot) & 7)][f];
        __nv_bfloat16 h = __float2bfloat16(acc);
        const size_t idx = (size_t)j * KDIM + q * FF + f;
        g_Bh[idx] = h;
        g_Bl[idx] = __float2bfloat16(acc - __bfloat162float(h));
    }
}

// ---------------------------------------------------------------------------
// Kernel 3: pipelined HMMA bf16 GEMM (128x256 block, K'=15360) + fused epilogue
// ---------------------------------------------------------------------------
__global__ void __launch_bounds__(256, 1)
gemm_mma(const float* __restrict__ bias, float* __restrict__ out)
{
    extern __shared__ char smem[];
    const uint32_t sbase = smem_u32(smem);

    const int tid = threadIdx.x;
    const int lid = tid & 31;
    const int wid = tid >> 5;
    const int wm  = wid >> 2;             // 0..1  -> 64 rows
    const int wn  = wid & 3;              // 0..3  -> 64 cols
    const int rot = blockIdx.x;           // fastest -> A-tile L2 reuse
    const int m0  = blockIdx.y * BM;
    const int n0  = rot * BN;

    const int grp = lid >> 3;             // ldmatrix 8-lane group
    const int wit = lid & 7;

    // ldmatrix smem byte offsets (within a stage buffer)
    const uint32_t aoffs = (uint32_t)((wm * 64 + (grp & 1) * 8 + wit) * (AST * 2)
                                      + (grp >> 1) * 16);
    const uint32_t boffs = (uint32_t)A_BYTES
                         + (uint32_t)((wn * 64 + (grp >> 1) * 8 + wit) * (AST * 2)
                                      + (grp & 1) * 16);

    // cp.async per-thread slots
    const int ar = (tid >> 2);            // +128 on second pass
    const int ac = (tid & 3);

    float acc[4][8][4];
    #pragma unroll
    for (int mt = 0; mt < 4; mt++)
        #pragma unroll
        for (int nt = 0; nt < 8; nt++)
            #pragma unroll
            for (int i = 0; i < 4; i++) acc[mt][nt][i] = 0.f;

    auto issue_stage = [&](int sp) {
        const int seg = sp / CPS;
        const int kk0 = (sp % CPS) * BK;
        const __nv_bfloat16* pa = (seg == 1) ? g_Al : g_Ah;
        const __nv_bfloat16* pb = (seg == 2) ? g_Bl : g_Bh;
        const uint32_t sb = sbase + (uint32_t)(sp & (NSTG - 1)) * STG_BYTES;
        // A: 128 rows x 32 bf16 (2 x 16B per thread)
        #pragma unroll
        for (int i = 0; i < 2; i++) {
            const int r  = ar + i * 64;
            const int gm = m0 + r;
            const bool v = gm < NV;
            const __nv_bfloat16* g = pa + (size_t)(v ? gm : 0) * KDIM + kk0 + ac * 8;
            cpasync16(sb + r * (AST * 2) + ac * 16, g, v ? 16 : 0);
        }
        // B: 256 rows x 32 bf16 (4 x 16B per thread)
        #pragma unroll
        for (int i = 0; i < 4; i++) {
            const int r = ar + i * 64;
            const __nv_bfloat16* g = pb + (size_t)(n0 + r) * KDIM + kk0 + ac * 8;
            cpasync16(sb + A_BYTES + r * (AST * 2) + ac * 16, g, 16);
        }
        CP_COMMIT();
    };

    issue_stage(0);
    issue_stage(1);
    issue_stage(2);

    for (int s = 0; s < NS; s++) {
        CP_WAIT2();
        __syncthreads();
        if (s + 3 < NS) issue_stage(s + 3); else CP_COMMIT();

        const uint32_t sb = sbase + (uint32_t)(s & (NSTG - 1)) * STG_BYTES;
        #pragma unroll
        for (int ks = 0; ks < 2; ks++) {
            uint32_t a[4][4], b[4][4];
            #pragma unroll
            for (int mt = 0; mt < 4; mt++)
                ldsm_x4(a[mt], sb + aoffs + mt * (16 * AST * 2) + ks * 32);
            #pragma unroll
            for (int np = 0; np < 4; np++)
                ldsm_x4(b[np], sb + boffs + np * (16 * AST * 2) + ks * 32);
            #pragma unroll
            for (int mt = 0; mt < 4; mt++) {
                #pragma unroll
                for (int np = 0; np < 4; np++) {
                    mma_bf16(acc[mt][2 * np],     a[mt], &b[np][0]);
                    mma_bf16(acc[mt][2 * np + 1], a[mt], &b[np][2]);
                }
            }
        }
    }
    __syncthreads();

    // ---------------- fused epilogue ----------------
    // warps wn>=2 hold k=1 columns: relu(v+40*b1) -> smem exchange
    // warps wn<2  hold k=0 columns: relu(v+40*b0) + ex -> out
    float* ex = (float*)smem;             // 128 x 132 f32 (padded, conflict-free)
    const int q4 = lid >> 2;
    const int r4 = lid & 3;

    if (wn >= 2) {
        #pragma unroll
        for (int mt = 0; mt < 4; mt++) {
            const int r = wm * 64 + mt * 16 + q4;
            #pragma unroll
            for (int nt = 0; nt < 8; nt++) {
                const int o = (wn - 2) * 64 + nt * 8 + r4 * 2;
                const float b1a = 40.f * __ldg(&bias[OO + o]);
                const float b1b = 40.f * __ldg(&bias[OO + o + 1]);
                ex[r * 132 + o]           = fmaxf(acc[mt][nt][0] + b1a, 0.f);
                ex[r * 132 + o + 1]       = fmaxf(acc[mt][nt][1] + b1b, 0.f);
                ex[(r + 8) * 132 + o]     = fmaxf(acc[mt][nt][2] + b1a, 0.f);
                ex[(r + 8) * 132 + o + 1] = fmaxf(acc[mt][nt][3] + b1b, 0.f);
            }
        }
    }
    __syncthreads();
    if (wn < 2) {
        #pragma unroll
        for (int mt = 0; mt < 4; mt++) {
            const int r  = wm * 64 + mt * 16 + q4;
            const int gm = m0 + r;
            #pragma unroll
            for (int nt = 0; nt < 8; nt++) {
                const int o = wn * 64 + nt * 8 + r4 * 2;
                const float b0a = 40.f * __ldg(&bias[o]);
                const float b0b = 40.f * __ldg(&bias[o + 1]);
                if (gm < NV) {
                    float* op = out + (size_t)gm * (NROT * OO) + rot * OO + o;
                    op[0] = fmaxf(acc[mt][nt][0] + b0a, 0.f) + ex[r * 132 + o];
                    op[1] = fmaxf(acc[mt][nt][1] + b0b, 0.f) + ex[r * 132 + o + 1];
                }
                if (gm + 8 < NV) {
                    float* op = out + (size_t)(gm + 8) * (NROT * OO) + rot * OO + o;
                    op[0] = fmaxf(acc[mt][nt][2] + b0a, 0.f) + ex[(r + 8) * 132 + o];
                    op[1] = fmaxf(acc[mt][nt][3] + b0b, 0.f) + ex[(r + 8) * 132 + o + 1];
                }
            }
        }
    }
}

// ---------------------------------------------------------------------------
extern "C" void kernel_launch(void* const* d_in, const int* in_sizes, int n_in,
                              void* d_out, int out_size)
{
    const float *ms = nullptr, *bary = nullptr, *W = nullptr,
                *bias = nullptr, *interp = nullptr;
    for (int i = 0; i < n_in; i++) {
        switch (in_sizes[i]) {
            case NV * FF:             ms     = (const float*)d_in[i]; break;
            case NV * RA * 3 * 2:     bary   = (const float*)d_in[i]; break;
            case RA * KK * OO * FF:   W      = (const float*)d_in[i]; break;
            case KK * OO:             bias   = (const float*)d_in[i]; break;
            case RA * RA:             interp = (const float*)d_in[i]; break;
            default: break;
        }
    }
    float* out = (float*)d_out;

    gather_bary<<<NV * RA, FF>>>(ms, bary);
    build_wc<<<NOUTJ, FF>>>(W, interp);

    cudaFuncSetAttribute(gemm_mma, cudaFuncAttributeMaxDynamicSharedMemorySize, DYNSMEM);
    dim3 gg(NROT, (NV + BM - 1) / BM);    // rot fastest: A-tile L2 reuse
    gemm_mma<<<gg, 256, DYNSMEM>>>(bias, out);
}

// round 5
// speedup vs baseline: 6.0304x; 3.2811x over previous
#include <cuda_runtime.h>
#include <cuda_fp16.h>
#include <cstdint>

// ---------------- problem constants ----------------
#define NV    6000
#define RR    5
#define AA    8
#define FF    128
#define KK    2
#define OO    128
#define RA    40
#define KDIM  5120
#define NROT  8
#define NOUTJ (NROT*KK*OO)        // 2048 GEMM columns, layout j = rot*256 + o*2 + k

// ---------------- GEMM tiling ----------------
#define BM    128
#define BN    256                 // one rot (all o, both k)
#define BK    64                  // fp16 per stage
#define NSTAGES (KDIM/BK)         // 80
#define ASTB  144                 // padded smem row stride bytes (9*16B -> ldsm conflict-free)
#define A_BYTES (BM*ASTB)         // 18432
#define B_BYTES (BN*ASTB)         // 36864
#define STG_BYTES (A_BYTES + B_BYTES)   // 55296
#define NSTG  3
#define DYNSMEM (NSTG*STG_BYTES)  // 165888

// ---------------- scratch ----------------
__device__ __half g_A[(size_t)NV * KDIM];      // 61.4 MB
__device__ __half g_B[(size_t)NOUTJ * KDIM];   // 21.0 MB

// ---------------- PTX helpers ----------------
__device__ __forceinline__ uint32_t smem_u32(const void* p) {
    uint32_t a;
    asm("{ .reg .u64 t; cvta.to.shared.u64 t, %1; cvt.u32.u64 %0, t; }"
        : "=r"(a) : "l"(p));
    return a;
}
__device__ __forceinline__ void cpasync16(uint32_t saddr, const void* g, int srcsz) {
    asm volatile("cp.async.cg.shared.global [%0], [%1], 16, %2;"
                 :: "r"(saddr), "l"(g), "r"(srcsz) : "memory");
}
#define CP_COMMIT() asm volatile("cp.async.commit_group;" ::: "memory")
#define CP_WAIT1()  asm volatile("cp.async.wait_group 1;" ::: "memory")

__device__ __forceinline__ void ldsm_x4(uint32_t* r, uint32_t addr) {
    asm volatile("ldmatrix.sync.aligned.m8n8.x4.shared.b16 {%0,%1,%2,%3}, [%4];"
                 : "=r"(r[0]), "=r"(r[1]), "=r"(r[2]), "=r"(r[3]) : "r"(addr));
}
__device__ __forceinline__ void mma_f16(float* d, const uint32_t* a, const uint32_t* b) {
    asm volatile(
        "mma.sync.aligned.m16n8k16.row.col.f32.f16.f16.f32 "
        "{%0,%1,%2,%3}, {%4,%5,%6,%7}, {%8,%9}, {%0,%1,%2,%3};"
        : "+f"(d[0]), "+f"(d[1]), "+f"(d[2]), "+f"(d[3])
        : "r"(a[0]), "r"(a[1]), "r"(a[2]), "r"(a[3]), "r"(b[0]), "r"(b[1]));
}

// ---------------------------------------------------------------------------
// Kernel 1: gather + barycentric -> fp16 A.  Warp per row; lane = float4 of f.
// ---------------------------------------------------------------------------
__global__ void __launch_bounds__(256)
gather_bary(const float* __restrict__ ms, const float* __restrict__ bary)
{
    const int wid  = threadIdx.x >> 5;
    const int lane = threadIdx.x & 31;
    const int row  = blockIdx.x * 8 + wid;          // n*RA + q
    if (row >= NV * RA) return;

    float bv = (lane < 6) ? bary[(size_t)row * 6 + lane] : 0.f;
    const int   i0 = (int)__shfl_sync(0xffffffffu, bv, 0);
    const float w0 =      __shfl_sync(0xffffffffu, bv, 1);
    const int   i1 = (int)__shfl_sync(0xffffffffu, bv, 2);
    const float w1 =      __shfl_sync(0xffffffffu, bv, 3);
    const int   i2 = (int)__shfl_sync(0xffffffffu, bv, 4);
    const float w2 =      __shfl_sync(0xffffffffu, bv, 5);

    const float4 a = __ldg((const float4*)(ms + (size_t)i0 * FF) + lane);
    const float4 b = __ldg((const float4*)(ms + (size_t)i1 * FF) + lane);
    const float4 c = __ldg((const float4*)(ms + (size_t)i2 * FF) + lane);

    float4 v;
    v.x = w0 * a.x + w1 * b.x + w2 * c.x;
    v.y = w0 * a.y + w1 * b.y + w2 * c.y;
    v.z = w0 * a.z + w1 * b.z + w2 * c.z;
    v.w = w0 * a.w + w1 * b.w + w2 * c.w;

    __half2 h01 = __floats2half2_rn(v.x, v.y);
    __half2 h23 = __floats2half2_rn(v.z, v.w);
    uint2 pk = make_uint2(*(uint32_t*)&h01, *(uint32_t*)&h23);
    *((uint2*)(g_A + (size_t)row * FF) + lane) = pk;   // row*FF == n*KDIM + q*FF
}

// ---------------------------------------------------------------------------
// Kernel 2: fold interp + rotation -> fp16 B, rows j = rot*256 + o*2 + k
// ---------------------------------------------------------------------------
__global__ void build_wc(const float* __restrict__ W,
                         const float* __restrict__ interp)
{
    const int j0  = blockIdx.x;           // 0..2047
    const int rot = j0 >> 8;
    const int k   = (j0 >> 7) & 1;
    const int o   = j0 & 127;
    const int f   = threadIdx.x;
    const int jr  = rot * 256 + o * 2 + k;   // output row (new layout)

    __shared__ float s_w[RA][FF];
    __shared__ float s_c[RA][RA];

    for (int ra = 0; ra < RA; ra++)
        s_w[ra][f] = W[(((size_t)ra * KK + k) * OO + o) * FF + f];
    for (int i = f; i < RA * RA; i += FF)
        s_c[i / RA][i % RA] = interp[i];
    __syncthreads();

    for (int q = 0; q < RA; q++) {
        float acc = 0.f;
        #pragma unroll
        for (int r = 0; r < RR; r++)
            #pragma unroll
            for (int b = 0; b < AA; b++)
                acc += s_c[r * AA + b][q] * s_w[r * AA + ((b + rot) & 7)][f];
        g_B[(size_t)jr * KDIM + q * FF + f] = __float2half_rn(acc);
    }
}

// ---------------------------------------------------------------------------
// Kernel 3: pipelined fp16 HMMA GEMM (128x256, K=5120) + register-local epilogue
// ---------------------------------------------------------------------------
__global__ void __launch_bounds__(256, 1)
gemm_mma(const float* __restrict__ bias, float* __restrict__ out)
{
    extern __shared__ char smem[];
    const uint32_t sbase = smem_u32(smem);

    const int tid = threadIdx.x;
    const int lid = tid & 31;
    const int wid = tid >> 5;
    const int wm  = wid >> 2;             // 0..1 -> 64 rows
    const int wn  = wid & 3;              // 0..3 -> 64 cols
    const int rot = blockIdx.x;           // fastest -> A-tile L2 reuse
    const int m0  = blockIdx.y * BM;
    const int n0  = rot * BN;

    const int grp = lid >> 3;
    const int wit = lid & 7;

    const uint32_t aoffs = (uint32_t)((wm * 64 + (grp & 1) * 8 + wit) * ASTB
                                      + (grp >> 1) * 16);
    const uint32_t boffs = (uint32_t)A_BYTES
                         + (uint32_t)((wn * 64 + (grp >> 1) * 8 + wit) * ASTB
                                      + (grp & 1) * 16);

    float acc[4][8][4];
    #pragma unroll
    for (int mt = 0; mt < 4; mt++)
        #pragma unroll
        for (int nt = 0; nt < 8; nt++)
            #pragma unroll
            for (int i = 0; i < 4; i++) acc[mt][nt][i] = 0.f;

    auto issue_stage = [&](int sp) {
        const int kk0 = sp * BK;
        const uint32_t sb = sbase + (uint32_t)(sp % NSTG) * STG_BYTES;
        // A: 128 rows x 64 fp16 (8 x 16B per row), 4 chunks/thread
        #pragma unroll
        for (int i = 0; i < 4; i++) {
            const int id  = tid + i * 256;
            const int r   = id >> 3;
            const int c16 = id & 7;
            const int gm  = m0 + r;
            const bool v  = gm < NV;
            const __half* g = g_A + (size_t)(v ? gm : 0) * KDIM + kk0 + c16 * 8;
            cpasync16(sb + r * ASTB + c16 * 16, g, v ? 16 : 0);
        }
        // B: 256 rows x 64 fp16, 8 chunks/thread
        #pragma unroll
        for (int i = 0; i < 8; i++) {
            const int id  = tid + i * 256;
            const int r   = id >> 3;
            const int c16 = id & 7;
            const __half* g = g_B + (size_t)(n0 + r) * KDIM + kk0 + c16 * 8;
            cpasync16(sb + A_BYTES + r * ASTB + c16 * 16, g, 16);
        }
        CP_COMMIT();
    };

    issue_stage(0);
    issue_stage(1);

    for (int s = 0; s < NSTAGES; s++) {
        CP_WAIT1();
        __syncthreads();
        if (s + 2 < NSTAGES) issue_stage(s + 2); else CP_COMMIT();

        const uint32_t sb = sbase + (uint32_t)(s % NSTG) * STG_BYTES;
        #pragma unroll
        for (int ks = 0; ks < 4; ks++) {            // 4 x k16 per 64-chunk
            uint32_t a[4][4], b[4][4];
            #pragma unroll
            for (int mt = 0; mt < 4; mt++)
                ldsm_x4(a[mt], sb + aoffs + mt * (16 * ASTB) + ks * 32);
            #pragma unroll
            for (int np = 0; np < 4; np++)
                ldsm_x4(b[np], sb + boffs + np * (16 * ASTB) + ks * 32);
            #pragma unroll
            for (int mt = 0; mt < 4; mt++) {
                #pragma unroll
                for (int np = 0; np < 4; np++) {
                    mma_f16(acc[mt][2 * np],     a[mt], &b[np][0]);
                    mma_f16(acc[mt][2 * np + 1], a[mt], &b[np][2]);
                }
            }
        }
        __syncthreads();
    }

    // ---------------- register-local epilogue ----------------
    // D-frag: thread holds cols {2*r4, 2*r4+1} = (o, k=0),(o, k=1) in the
    // j = rot*256 + o*2 + k layout -> out = relu(v0+40b0)+relu(v1+40b1).
    const int q4 = lid >> 2;
    const int r4 = lid & 3;
    #pragma unroll
    for (int mt = 0; mt < 4; mt++) {
        const int r  = wm * 64 + mt * 16 + q4;
        const int gm = m0 + r;
        #pragma unroll
        for (int nt = 0; nt < 8; nt++) {
            const int o  = wn * 32 + nt * 4 + r4;    // (wn*64+nt*8+2*r4)/2
            const float b0 = 40.f * __ldg(&bias[o]);
            const float b1 = 40.f * __ldg(&bias[OO + o]);
            if (gm < NV)
                out[(size_t)gm * (NROT * OO) + rot * OO + o] =
                    fmaxf(acc[mt][nt][0] + b0, 0.f) + fmaxf(acc[mt][nt][1] + b1, 0.f);
            if (gm + 8 < NV)
                out[(size_t)(gm + 8) * (NROT * OO) + rot * OO + o] =
                    fmaxf(acc[mt][nt][2] + b0, 0.f) + fmaxf(acc[mt][nt][3] + b1, 0.f);
        }
    }
}

// ---------------------------------------------------------------------------
extern "C" void kernel_launch(void* const* d_in, const int* in_sizes, int n_in,
                              void* d_out, int out_size)
{
    const float *ms = nullptr, *bary = nullptr, *W = nullptr,
                *bias = nullptr, *interp = nullptr;
    for (int i = 0; i < n_in; i++) {
        switch (in_sizes[i]) {
            case NV * FF:             ms     = (const float*)d_in[i]; break;
            case NV * RA * 3 * 2:     bary   = (const float*)d_in[i]; break;
            case RA * KK * OO * FF:   W      = (const float*)d_in[i]; break;
            case KK * OO:             bias   = (const float*)d_in[i]; break;
            case RA * RA:             interp = (const float*)d_in[i]; break;
            default: break;
        }
    }
    float* out = (float*)d_out;

    gather_bary<<<(NV * RA + 7) / 8, 256>>>(ms, bary);
    build_wc<<<NOUTJ, FF>>>(W, interp);

    cudaFuncSetAttribute(gemm_mma, cudaFuncAttributeMaxDynamicSharedMemorySize, DYNSMEM);
    dim3 gg(NROT, (NV + BM - 1) / BM);
    gemm_mma<<<gg, 256, DYNSMEM>>>(bias, out);
}

// round 8
// speedup vs baseline: 13.6400x; 2.2619x over previous
#include <cuda_runtime.h>
#include <cuda_fp16.h>
#include <cstdint>

// ---------------- problem constants ----------------
#define NV    6000
#define RR    5
#define AA    8
#define FF    128
#define KK    2
#define OO    128
#define RA    40
#define KDIM  5120
#define NROT  8
#define NJ    2048                // spectral output columns

// ---------------- GEMM tiling ----------------
#define BM    128
#define BN    256
#define BK    64
#define ASTB  144                 // padded smem row stride bytes (9*16B, ldsm conflict-free)
#define A_BYTES (BM*ASTB)         // 18432
#define B_BYTES (BN*ASTB)         // 36864
#define STG_BYTES (A_BYTES + B_BYTES)
#define NSTG  3
#define DYNSMEM (NSTG*STG_BYTES)  // 165888

// ---------------- scratch ----------------
__device__ __half g_A[(size_t)NV * KDIM];      // spectral A' (fp16)
__device__ __half g_B[(size_t)NJ * KDIM];      // spectral B  (fp16, row stride KDIM, first Kg used)
__device__ float  g_S[(size_t)NV * NJ];        // GEMM result (spectral)
__device__ float  g_M[RA * RA];                // FFT∘interp fold (40x40)

// ---------------- PTX helpers ----------------
__device__ __forceinline__ uint32_t smem_u32(const void* p) {
    uint32_t a;
    asm("{ .reg .u64 t; cvta.to.shared.u64 t, %1; cvt.u32.u64 %0, t; }"
        : "=r"(a) : "l"(p));
    return a;
}
__device__ __forceinline__ void cpasync16(uint32_t saddr, const void* g, int srcsz) {
    asm volatile("cp.async.cg.shared.global [%0], [%1], 16, %2;"
                 :: "r"(saddr), "l"(g), "r"(srcsz) : "memory");
}
#define CP_COMMIT() asm volatile("cp.async.commit_group;" ::: "memory")
#define CP_WAIT1()  asm volatile("cp.async.wait_group 1;" ::: "memory")

__device__ __forceinline__ void ldsm_x4(uint32_t* r, uint32_t addr) {
    asm volatile("ldmatrix.sync.aligned.m8n8.x4.shared.b16 {%0,%1,%2,%3}, [%4];"
                 : "=r"(r[0]), "=r"(r[1]), "=r"(r[2]), "=r"(r[3]) : "r"(addr));
}
__device__ __forceinline__ void mma_f16(float* d, const uint32_t* a, const uint32_t* b) {
    asm volatile(
        "mma.sync.aligned.m16n8k16.row.col.f32.f16.f16.f32 "
        "{%0,%1,%2,%3}, {%4,%5,%6,%7}, {%8,%9}, {%0,%1,%2,%3};"
        : "+f"(d[0]), "+f"(d[1]), "+f"(d[2]), "+f"(d[3])
        : "r"(a[0]), "r"(a[1]), "r"(a[2]), "r"(a[3]), "r"(b[0]), "r"(b[1]));
}

// ---------------------------------------------------------------------------
// Kernel 0: M[p][q] = sum_b coef(comp(p), b) * interp[r_p, b, q]
//   p = comp*5 + r;  comp: 0=w0, 1=w1re, 2=w1im, 3=w2re, 4=w2im,
//                          5=w3re, 6=w3im, 7=w4.  (e^{-i..}: im uses -sin)
// ---------------------------------------------------------------------------
__global__ void make_M(const float* __restrict__ interp)
{
    const int e = blockIdx.x * 256 + threadIdx.x;
    if (e >= RA * RA) return;
    const int p = e / RA, q = e % RA;
    const int comp = p / RR, r = p % RR;
    float acc = 0.f;
    #pragma unroll
    for (int b = 0; b < AA; b++) {
        float coef;
        if (comp == 0)      coef = 1.f;
        else if (comp == 7) coef = (b & 1) ? -1.f : 1.f;
        else {
            const int m = (comp + 1) >> 1;         // 1,1,2,2,3,3
            const float x = 0.25f * (float)(m * b);
            coef = (comp & 1) ? cospif(x) : -sinpif(x);
        }
        acc += coef * interp[r * (AA * RA) + b * RA + q];
    }
    g_M[p * RA + q] = acc;
}

// ---------------------------------------------------------------------------
// Kernel 1: fused gather + barycentric + (FFT∘interp) -> spectral A' fp16
//   A'[n, p*128+f] = sum_q M[p,q] * sig[n,q,f]
// ---------------------------------------------------------------------------
__global__ void __launch_bounds__(256)
gatherA(const float* __restrict__ ms, const float* __restrict__ bary)
{
    const int n    = blockIdx.x;
    const int tid  = threadIdx.x;
    const int wid  = tid >> 5;
    const int lane = tid & 31;

    __shared__ float s_sig[RA][FF];
    __shared__ float s_M[RA][RA];

    for (int i = tid; i < RA * RA; i += 256)
        s_M[i / RA][i % RA] = g_M[i];

    #pragma unroll
    for (int it = 0; it < 5; it++) {
        const int q   = wid + 8 * it;
        const int row = n * RA + q;
        float bv = (lane < 6) ? bary[(size_t)row * 6 + lane] : 0.f;
        const int   i0 = (int)__shfl_sync(0xffffffffu, bv, 0);
        const float w0 =      __shfl_sync(0xffffffffu, bv, 1);
        const int   i1 = (int)__shfl_sync(0xffffffffu, bv, 2);
        const float w1 =      __shfl_sync(0xffffffffu, bv, 3);
        const int   i2 = (int)__shfl_sync(0xffffffffu, bv, 4);
        const float w2 =      __shfl_sync(0xffffffffu, bv, 5);

        const float4 a = __ldg((const float4*)(ms + (size_t)i0 * FF) + lane);
        const float4 b = __ldg((const float4*)(ms + (size_t)i1 * FF) + lane);
        const float4 c = __ldg((const float4*)(ms + (size_t)i2 * FF) + lane);
        s_sig[q][lane * 4 + 0] = w0 * a.x + w1 * b.x + w2 * c.x;
        s_sig[q][lane * 4 + 1] = w0 * a.y + w1 * b.y + w2 * c.y;
        s_sig[q][lane * 4 + 2] = w0 * a.z + w1 * b.z + w2 * c.z;
        s_sig[q][lane * 4 + 3] = w0 * a.w + w1 * b.w + w2 * c.w;
    }
    __syncthreads();

    const int f  = tid & 127;
    const int ph = tid >> 7;                 // 0..1
    float sr[RA];
    #pragma unroll
    for (int q = 0; q < RA; q++) sr[q] = s_sig[q][f];

    for (int p = ph; p < RA; p += 2) {
        float acc = 0.f;
        #pragma unroll
        for (int q = 0; q < RA; q++)
            acc = fmaf(s_M[p][q], sr[q], acc);
        g_A[(size_t)n * KDIM + p * FF + f] = __float2half_rn(acc);
    }
}

// ---------------------------------------------------------------------------
// Kernel 2: spectral B build.  Block = om*256 + k*128 + o (om = 0..4).
//   w_hat_r[r] =  scale * sum_b cos(pi*om*b/4) * W[r,b,k,o,f]
//   w_hat_i[r] = -scale * sum_b sin(pi*om*b/4) * W[r,b,k,o,f]
// rows: om=0 -> j=k*128+o (K=640, entries = (1/8)*whr)
//       om=4 -> j=1792+k*128+o (K=640, (1/8)*sum(-1)^b W)
//       om=1..3 -> jr=(2*om-1)*256+k*128+o : [whr | whi]*1/4
//                  ji=jr+256                : [whi | -whr]*1/4
// ---------------------------------------------------------------------------
__global__ void buildB(const float* __restrict__ W)
{
    const int bid = blockIdx.x;
    const int om  = bid >> 8;
    const int k   = (bid >> 7) & 1;
    const int o   = bid & 127;
    const int f   = threadIdx.x;

    float w[RR][AA];
    #pragma unroll
    for (int r = 0; r < RR; r++)
        #pragma unroll
        for (int b = 0; b < AA; b++)
            w[r][b] = __ldg(&W[((((size_t)(r * AA + b)) * KK + k) * OO + o) * FF + f]);

    if (om == 0) {
        const int j = k * OO + o;
        #pragma unroll
        for (int r = 0; r < RR; r++) {
            float s = 0.f;
            #pragma unroll
            for (int b = 0; b < AA; b++) s += w[r][b];
            g_B[(size_t)j * KDIM + r * FF + f] = __float2half_rn(0.125f * s);
        }
    } else if (om == 4) {
        const int j = 7 * 256 + k * OO + o;
        #pragma unroll
        for (int r = 0; r < RR; r++) {
            float s = 0.f;
            #pragma unroll
            for (int b = 0; b < AA; b++) s += ((b & 1) ? -w[r][b] : w[r][b]);
            g_B[(size_t)j * KDIM + r * FF + f] = __float2half_rn(0.125f * s);
        }
    } else {
        const int jr = (2 * om - 1) * 256 + k * OO + o;
        const int ji = jr + 256;
        #pragma unroll
        for (int r = 0; r < RR; r++) {
            float sr = 0.f, si = 0.f;
            #pragma unroll
            for (int b = 0; b < AA; b++) {
                const float x = 0.25f * (float)(om * b);
                sr = fmaf(cospif(x), w[r][b], sr);
                si = fmaf(-sinpif(x), w[r][b], si);
            }
            const float whr = 0.25f * sr, whi = 0.25f * si;
            g_B[(size_t)jr * KDIM + r * FF + f]       = __float2half_rn(whr);
            g_B[(size_t)jr * KDIM + 640 + r * FF + f] = __float2half_rn(whi);
            g_B[(size_t)ji * KDIM + r * FF + f]       = __float2half_rn(whi);
            g_B[(size_t)ji * KDIM + 640 + r * FF + f] = __float2half_rn(-whr);
        }
    }
}

// ---------------------------------------------------------------------------
// Kernel 3: block-diagonal spectral GEMM.  Group g = blockIdx.x:
//   g=0: om0 (K=640, A cols 0..640), g=1,2: om1 re/im (K=1280, A 640..1920),
//   g=3,4: om2 (1920..3200), g=5,6: om3 (3200..4480), g=7: om4 (4480..5120).
// ---------------------------------------------------------------------------
__global__ void __launch_bounds__(256, 1)
gemm_mma()
{
    extern __shared__ char smem[];
    const uint32_t sbase = smem_u32(smem);

    const int tid = threadIdx.x;
    const int lid = tid & 31;
    const int wid = tid >> 5;
    const int wm  = wid >> 2;
    const int wn  = wid & 3;
    const int g   = blockIdx.x;
    const int m0  = blockIdx.y * BM;
    const int n0  = g * 256;              // B row base

    const int Kg   = (g == 0 || g == 7) ? 640 : 1280;
    const int ns   = Kg / BK;             // 10 or 20
    const int aoff = (g == 0) ? 0 : (g <= 2) ? 640 : (g <= 4) ? 1920
                   : (g <= 6) ? 3200 : 4480;

    const int grp = lid >> 3;
    const int wit = lid & 7;
    const uint32_t aoffs = (uint32_t)((wm * 64 + (grp & 1) * 8 + wit) * ASTB
                                      + (grp >> 1) * 16);
    const uint32_t boffs = (uint32_t)A_BYTES
                         + (uint32_t)((wn * 64 + (grp >> 1) * 8 + wit) * ASTB
                                      + (grp & 1) * 16);

    float acc[4][8][4];
    #pragma unroll
    for (int mt = 0; mt < 4; mt++)
        #pragma unroll
        for (int nt = 0; nt < 8; nt++)
            #pragma unroll
            for (int i = 0; i < 4; i++) acc[mt][nt][i] = 0.f;

    auto issue_stage = [&](int sp) {
        const int kk0 = sp * BK;
        const uint32_t sb = sbase + (uint32_t)(sp % NSTG) * STG_BYTES;
        #pragma unroll
        for (int i = 0; i < 4; i++) {
            const int id  = tid + i * 256;
            const int r   = id >> 3;
            const int c16 = id & 7;
            const int gm  = m0 + r;
            const bool v  = gm < NV;
            const __half* gp = g_A + (size_t)(v ? gm : 0) * KDIM + aoff + kk0 + c16 * 8;
            cpasync16(sb + r * ASTB + c16 * 16, gp, v ? 16 : 0);
        }
        #pragma unroll
        for (int i = 0; i < 8; i++) {
            const int id  = tid + i * 256;
            const int r   = id >> 3;
            const int c16 = id & 7;
            const __half* gp = g_B + (size_t)(n0 + r) * KDIM + kk0 + c16 * 8;
            cpasync16(sb + A_BYTES + r * ASTB + c16 * 16, gp, 16);
        }
        CP_COMMIT();
    };

    issue_stage(0);
    issue_stage(1);

    for (int s = 0; s < ns; s++) {
        CP_WAIT1();
        __syncthreads();
        if (s + 2 < ns) issue_stage(s + 2); else CP_COMMIT();

        const uint32_t sb = sbase + (uint32_t)(s % NSTG) * STG_BYTES;
        #pragma unroll
        for (int ks = 0; ks < 4; ks++) {
            uint32_t a[4][4], b[4][4];
            #pragma unroll
            for (int mt = 0; mt < 4; mt++)
                ldsm_x4(a[mt], sb + aoffs + mt * (16 * ASTB) + ks * 32);
            #pragma unroll
            for (int np = 0; np < 4; np++)
                ldsm_x4(b[np], sb + boffs + np * (16 * ASTB) + ks * 32);
            #pragma unroll
            for (int mt = 0; mt < 4; mt++) {
                #pragma unroll
                for (int np = 0; np < 4; np++) {
                    mma_f16(acc[mt][2 * np],     a[mt], &b[np][0]);
                    mma_f16(acc[mt][2 * np + 1], a[mt], &b[np][2]);
                }
            }
        }
    }

    // store spectral result
    const int q4 = lid >> 2;
    const int r4 = lid & 3;
    #pragma unroll
    for (int mt = 0; mt < 4; mt++) {
        const int r  = wm * 64 + mt * 16 + q4;
        const int gm = m0 + r;
        #pragma unroll
        for (int nt = 0; nt < 8; nt++) {
            const int c = wn * 64 + nt * 8 + 2 * r4;
            if (gm < NV)
                *(float2*)&g_S[(size_t)gm * NJ + n0 + c] =
                    make_float2(acc[mt][nt][0], acc[mt][nt][1]);
            if (gm + 8 < NV)
                *(float2*)&g_S[(size_t)(gm + 8) * NJ + n0 + c] =
                    make_float2(acc[mt][nt][2], acc[mt][nt][3]);
        }
    }
}

// ---------------------------------------------------------------------------
// Kernel 4: inverse FFT over omega + bias + relu + k-sum
//   s[rot] = C0 + (-1)^rot C4 + sum_{om=1..3} (CR*cos(om*rot*pi/4) - CI*sin)
// ---------------------------------------------------------------------------
__global__ void epilogue(const float* __restrict__ bias, float* __restrict__ out)
{
    const int n = blockIdx.x;
    const int o = threadIdx.x;
    const float* S = g_S + (size_t)n * NJ;

    float C[8][2];
    #pragma unroll
    for (int gg = 0; gg < 8; gg++)
        #pragma unroll
        for (int k = 0; k < 2; k++)
            C[gg][k] = S[gg * 256 + k * OO + o];

    const float ct[8] = {1.f, 0.70710678f, 0.f, -0.70710678f,
                         -1.f, -0.70710678f, 0.f, 0.70710678f};
    const float st[8] = {0.f, 0.70710678f, 1.f, 0.70710678f,
                         0.f, -0.70710678f, -1.f, -0.70710678f};
    const float b0 = 40.f * __ldg(&bias[o]);
    const float b1 = 40.f * __ldg(&bias[OO + o]);

    #pragma unroll
    for (int rot = 0; rot < 8; rot++) {
        const float sgn = (rot & 1) ? -1.f : 1.f;
        float s0 = C[0][0] + sgn * C[7][0]
                 + C[1][0] * ct[rot]           - C[2][0] * st[rot]
                 + C[3][0] * ct[(2 * rot) & 7] - C[4][0] * st[(2 * rot) & 7]
                 + C[5][0] * ct[(3 * rot) & 7] - C[6][0] * st[(3 * rot) & 7];
        float s1 = C[0][1] + sgn * C[7][1]
                 + C[1][1] * ct[rot]           - C[2][1] * st[rot]
                 + C[3][1] * ct[(2 * rot) & 7] - C[4][1] * st[(2 * rot) & 7]
                 + C[5][1] * ct[(3 * rot) & 7] - C[6][1] * st[(3 * rot) & 7];
        out[(size_t)n * (NROT * OO) + rot * OO + o] =
            fmaxf(s0 + b0, 0.f) + fmaxf(s1 + b1, 0.f);
    }
}

// ---------------------------------------------------------------------------
extern "C" void kernel_launch(void* const* d_in, const int* in_sizes, int n_in,
                              void* d_out, int out_size)
{
    const float *ms = nullptr, *bary = nullptr, *W = nullptr,
                *bias = nullptr, *interp = nullptr;
    for (int i = 0; i < n_in; i++) {
        switch (in_sizes[i]) {
            case NV * FF:             ms     = (const float*)d_in[i]; break;
            case NV * RA * 3 * 2:     bary   = (const float*)d_in[i]; break;
            case RA * KK * OO * FF:   W      = (const float*)d_in[i]; break;
            case KK * OO:             bias   = (const float*)d_in[i]; break;
            case RA * RA:             interp = (const float*)d_in[i]; break;
            default: break;
        }
    }
    float* out = (float*)d_out;

    make_M<<<(RA * RA + 255) / 256, 256>>>(interp);
    gatherA<<<NV, 256>>>(ms, bary);
    buildB<<<5 * 256, FF>>>(W);

    cudaFuncSetAttribute(gemm_mma, cudaFuncAttributeMaxDynamicSharedMemorySize, DYNSMEM);
    dim3 gg(8, (NV + BM - 1) / BM);
    gemm_mma<<<gg, 256, DYNSMEM>>>();

    epilogue<<<NV, OO>>>(bias, out);
}

// round 10
// speedup vs baseline: 14.2690x; 1.0461x over previous
#include <cuda_runtime.h>
#include <cuda_fp16.h>
#include <cstdint>

// ---------------- problem constants ----------------
#define NV    6000
#define RR    5
#define AA    8
#define FF    128
#define KK    2
#define OO    128
#define RA    40
#define KDIM  5120
#define NROT  8
#define NJ    2048                // spectral output columns

// ---------------- GEMM tiling ----------------
#define BM    128
#define BN    128
#define BK    64
#define ASTB  144                 // padded smem row stride bytes (9*16B, ldsm conflict-free)
#define A_BYTES (BM*ASTB)         // 18432
#define B_BYTES (BN*ASTB)         // 18432
#define STG_BYTES (A_BYTES + B_BYTES)   // 36864
#define NSTG  3
#define DYNSMEM (NSTG*STG_BYTES)  // 110592 -> 2 CTAs/SM

// ---------------- scratch ----------------
__device__ __half g_A[(size_t)NV * KDIM];      // spectral A' (fp16)
__device__ __half g_B[(size_t)NJ * KDIM];      // spectral B  (fp16)
__device__ float  g_S[(size_t)NV * NJ];        // spectral GEMM result
__device__ float  g_M[RA * RA];                // FFT∘interp fold (40x40)

// ---------------- PTX helpers ----------------
__device__ __forceinline__ uint32_t smem_u32(const void* p) {
    uint32_t a;
    asm("{ .reg .u64 t; cvta.to.shared.u64 t, %1; cvt.u32.u64 %0, t; }"
        : "=r"(a) : "l"(p));
    return a;
}
__device__ __forceinline__ void cpasync16(uint32_t saddr, const void* g, int srcsz) {
    asm volatile("cp.async.cg.shared.global [%0], [%1], 16, %2;"
                 :: "r"(saddr), "l"(g), "r"(srcsz) : "memory");
}
#define CP_COMMIT() asm volatile("cp.async.commit_group;" ::: "memory")
#define CP_WAIT1()  asm volatile("cp.async.wait_group 1;" ::: "memory")

__device__ __forceinline__ void ldsm_x4(uint32_t* r, uint32_t addr) {
    asm volatile("ldmatrix.sync.aligned.m8n8.x4.shared.b16 {%0,%1,%2,%3}, [%4];"
                 : "=r"(r[0]), "=r"(r[1]), "=r"(r[2]), "=r"(r[3]) : "r"(addr));
}
__device__ __forceinline__ void mma_f16(float* d, const uint32_t* a, const uint32_t* b) {
    asm volatile(
        "mma.sync.aligned.m16n8k16.row.col.f32.f16.f16.f32 "
        "{%0,%1,%2,%3}, {%4,%5,%6,%7}, {%8,%9}, {%0,%1,%2,%3};"
        : "+f"(d[0]), "+f"(d[1]), "+f"(d[2]), "+f"(d[3])
        : "r"(a[0]), "r"(a[1]), "r"(a[2]), "r"(a[3]), "r"(b[0]), "r"(b[1]));
}
// packed fp32x2 FMA (Blackwell FFMA2)
__device__ __forceinline__ unsigned long long fma_f32x2(
    unsigned long long a, unsigned long long b, unsigned long long c) {
    unsigned long long d;
    asm("fma.rn.f32x2 %0, %1, %2, %3;" : "=l"(d) : "l"(a), "l"(b), "l"(c));
    return d;
}

// ---------------------------------------------------------------------------
// Kernel 0: M[p][q] = sum_b coef(comp(p), b) * interp[r_p, b, q]
//   p = comp*5 + r;  comp: 0=w0, 1=w1re, 2=w1im, 3=w2re, 4=w2im,
//                          5=w3re, 6=w3im, 7=w4.  (e^{-i..}: im uses -sin)
// ---------------------------------------------------------------------------
__global__ void make_M(const float* __restrict__ interp)
{
    const int e = blockIdx.x * 256 + threadIdx.x;
    if (e >= RA * RA) return;
    const int p = e / RA, q = e % RA;
    const int comp = p / RR, r = p % RR;
    float acc = 0.f;
    #pragma unroll
    for (int b = 0; b < AA; b++) {
        float coef;
        if (comp == 0)      coef = 1.f;
        else if (comp == 7) coef = (b & 1) ? -1.f : 1.f;
        else {
            const int m = (comp + 1) >> 1;
            const float x = 0.25f * (float)(m * b);
            coef = (comp & 1) ? cospif(x) : -sinpif(x);
        }
        acc += coef * interp[r * (AA * RA) + b * RA + q];
    }
    g_M[p * RA + q] = acc;
}

// ---------------------------------------------------------------------------
// Kernel 1: fused gather + barycentric + (FFT∘interp) -> spectral A' fp16
//   A'[n, p*128+f] = sum_q M[p,q] * sig[n,q,f]   (packed f32x2 mainloop)
// ---------------------------------------------------------------------------
__global__ void __launch_bounds__(256)
gatherA(const float* __restrict__ ms, const float* __restrict__ bary)
{
    const int n    = blockIdx.x;
    const int tid  = threadIdx.x;
    const int wid  = tid >> 5;
    const int lane = tid & 31;

    __shared__ float s_sig[RA][FF];                 // 20.5 KB
    __shared__ unsigned long long s_M2[RA][RA];     // 12.8 KB (dup-packed M)

    for (int i = tid; i < RA * RA; i += 256) {
        const float m = g_M[i];
        float2 t = make_float2(m, m);
        s_M2[i / RA][i % RA] = *(unsigned long long*)&t;
    }

    #pragma unroll
    for (int it = 0; it < 5; it++) {
        const int q   = wid + 8 * it;
        const int row = n * RA + q;
        float bv = (lane < 6) ? bary[(size_t)row * 6 + lane] : 0.f;
        const int   i0 = (int)__shfl_sync(0xffffffffu, bv, 0);
        const float w0 =      __shfl_sync(0xffffffffu, bv, 1);
        const int   i1 = (int)__shfl_sync(0xffffffffu, bv, 2);
        const float w1 =      __shfl_sync(0xffffffffu, bv, 3);
        const int   i2 = (int)__shfl_sync(0xffffffffu, bv, 4);
        const float w2 =      __shfl_sync(0xffffffffu, bv, 5);

        const float4 a = __ldg((const float4*)(ms + (size_t)i0 * FF) + lane);
        const float4 b = __ldg((const float4*)(ms + (size_t)i1 * FF) + lane);
        const float4 c = __ldg((const float4*)(ms + (size_t)i2 * FF) + lane);
        s_sig[q][lane * 4 + 0] = w0 * a.x + w1 * b.x + w2 * c.x;
        s_sig[q][lane * 4 + 1] = w0 * a.y + w1 * b.y + w2 * c.y;
        s_sig[q][lane * 4 + 2] = w0 * a.z + w1 * b.z + w2 * c.z;
        s_sig[q][lane * 4 + 3] = w0 * a.w + w1 * b.w + w2 * c.w;
    }
    __syncthreads();

    const int fp    = tid & 63;          // f-pair: covers f = 2fp, 2fp+1
    const int phase = tid >> 6;          // 0..3 -> 10 p-rows each

    unsigned long long sr2[RA];
    #pragma unroll
    for (int q = 0; q < RA; q++)
        sr2[q] = *(const unsigned long long*)&s_sig[q][fp * 2];

    #pragma unroll
    for (int j = 0; j < 10; j++) {
        const int p = phase * 10 + j;
        unsigned long long acc = 0ull;   // packed (0,0)
        #pragma unroll
        for (int q = 0; q < RA; q++)
            acc = fma_f32x2(s_M2[p][q], sr2[q], acc);
        float2 v = *(float2*)&acc;
        *(__half2*)(g_A + (size_t)n * KDIM + p * FF + fp * 2) =
            __floats2half2_rn(v.x, v.y);
    }
}

// ---------------------------------------------------------------------------
// Kernel 2: spectral B build.  Block = om*256 + k*128 + o (om = 0..4).
// rows: om=0 -> j=k*128+o (K=640, (1/8)*whr)
//       om=4 -> j=1792+k*128+o (K=640, (1/8)*sum(-1)^b W)
//       om=1..3 -> jr=(2*om-1)*256+k*128+o : [whr | whi]*1/4
//                  ji=jr+256                : [whi | -whr]*1/4
// ---------------------------------------------------------------------------
__global__ void buildB(const float* __restrict__ W)
{
    const int bid = blockIdx.x;
    const int om  = bid >> 8;
    const int k   = (bid >> 7) & 1;
    const int o   = bid & 127;
    const int f   = threadIdx.x;

    float w[RR][AA];
    #pragma unroll
    for (int r = 0; r < RR; r++)
        #pragma unroll
        for (int b = 0; b < AA; b++)
            w[r][b] = __ldg(&W[((((size_t)(r * AA + b)) * KK + k) * OO + o) * FF + f]);

    if (om == 0) {
        const int j = k * OO + o;
        #pragma unroll
        for (int r = 0; r < RR; r++) {
            float s = 0.f;
            #pragma unroll
            for (int b = 0; b < AA; b++) s += w[r][b];
            g_B[(size_t)j * KDIM + r * FF + f] = __float2half_rn(0.125f * s);
        }
    } else if (om == 4) {
        const int j = 7 * 256 + k * OO + o;
        #pragma unroll
        for (int r = 0; r < RR; r++) {
            float s = 0.f;
            #pragma unroll
            for (int b = 0; b < AA; b++) s += ((b & 1) ? -w[r][b] : w[r][b]);
            g_B[(size_t)j * KDIM + r * FF + f] = __float2half_rn(0.125f * s);
        }
    } else {
        const int jr = (2 * om - 1) * 256 + k * OO + o;
        const int ji = jr + 256;
        #pragma unroll
        for (int r = 0; r < RR; r++) {
            float sr = 0.f, si = 0.f;
            #pragma unroll
            for (int b = 0; b < AA; b++) {
                const float x = 0.25f * (float)(om * b);
                sr = fmaf(cospif(x), w[r][b], sr);
                si = fmaf(-sinpif(x), w[r][b], si);
            }
            const float whr = 0.25f * sr, whi = 0.25f * si;
            g_B[(size_t)jr * KDIM + r * FF + f]       = __float2half_rn(whr);
            g_B[(size_t)jr * KDIM + 640 + r * FF + f] = __float2half_rn(whi);
            g_B[(size_t)ji * KDIM + r * FF + f]       = __float2half_rn(whi);
            g_B[(size_t)ji * KDIM + 640 + r * FF + f] = __float2half_rn(-whr);
        }
    }
}

// ---------------------------------------------------------------------------
// Kernel 3: block-diagonal spectral GEMM, 128x128 tiles, 2 CTAs/SM.
//   cg = blockIdx.x (heavy groups first): cg<12 -> g=1+cg/2 (K=1280),
//   cg 12,13 -> g=0; cg 14,15 -> g=7 (K=640). half = cg&1 -> n-offset.
// ---------------------------------------------------------------------------
__global__ void __launch_bounds__(256, 2)
gemm_mma()
{
    extern __shared__ char smem[];
    const uint32_t sbase = smem_u32(smem);

    const int tid = threadIdx.x;
    const int lid = tid & 31;
    const int wid = tid >> 5;
    const int wm  = wid >> 2;             // 0..1 -> 64 rows
    const int wn  = wid & 3;              // 0..3 -> 32 cols
    const int cg  = blockIdx.x;           // heavy-first order
    const int m0  = blockIdx.y * BM;

    int g, half;
    if (cg < 12) { g = 1 + (cg >> 1); half = cg & 1; }
    else if (cg < 14) { g = 0; half = cg & 1; }
    else { g = 7; half = cg & 1; }
    const int n0 = g * 256 + half * 128;  // B row / g_S col base

    const int Kg   = (g == 0 || g == 7) ? 640 : 1280;
    const int ns   = Kg / BK;             // 10 or 20
    const int aoff = (g == 0) ? 0 : (g <= 2) ? 640 : (g <= 4) ? 1920
                   : (g <= 6) ? 3200 : 4480;

    const int grp = lid >> 3;
    const int wit = lid & 7;
    const uint32_t aoffs = (uint32_t)((wm * 64 + (grp & 1) * 8 + wit) * ASTB
                                      + (grp >> 1) * 16);
    const uint32_t boffs = (uint32_t)A_BYTES
                         + (uint32_t)((wn * 32 + (grp >> 1) * 8 + wit) * ASTB
                                      + (grp & 1) * 16);

    float acc[4][4][4];
    #pragma unroll
    for (int mt = 0; mt < 4; mt++)
        #pragma unroll
        for (int nt = 0; nt < 4; nt++)
            #pragma unroll
            for (int i = 0; i < 4; i++) acc[mt][nt][i] = 0.f;

    auto issue_stage = [&](int sp) {
        const int kk0 = sp * BK;
        const uint32_t sb = sbase + (uint32_t)(sp % NSTG) * STG_BYTES;
        #pragma unroll
        for (int i = 0; i < 4; i++) {
            const int id  = tid + i * 256;
            const int r   = id >> 3;
            const int c16 = id & 7;
            const int gm  = m0 + r;
            const bool v  = gm < NV;
            const __half* gp = g_A + (size_t)(v ? gm : 0) * KDIM + aoff + kk0 + c16 * 8;
            cpasync16(sb + r * ASTB + c16 * 16, gp, v ? 16 : 0);
        }
        #pragma unroll
        for (int i = 0; i < 4; i++) {
            const int id  = tid + i * 256;
            const int r   = id >> 3;
            const int c16 = id & 7;
            const __half* gp = g_B + (size_t)(n0 + r) * KDIM + kk0 + c16 * 8;
            cpasync16(sb + A_BYTES + r * ASTB + c16 * 16, gp, 16);
        }
        CP_COMMIT();
    };

    issue_stage(0);
    issue_stage(1);

    for (int s = 0; s < ns; s++) {
        CP_WAIT1();
        __syncthreads();
        if (s + 2 < ns) issue_stage(s + 2); else CP_COMMIT();

        const uint32_t sb = sbase + (uint32_t)(s % NSTG) * STG_BYTES;
        #pragma unroll
        for (int ks = 0; ks < 4; ks++) {
            uint32_t a[4][4], b[2][4];
            #pragma unroll
            for (int mt = 0; mt < 4; mt++)
                ldsm_x4(a[mt], sb + aoffs + mt * (16 * ASTB) + ks * 32);
            #pragma unroll
            for (int np = 0; np < 2; np++)
                ldsm_x4(b[np], sb + boffs + np * (16 * ASTB) + ks * 32);
            #pragma unroll
            for (int mt = 0; mt < 4; mt++) {
                #pragma unroll
                for (int np = 0; np < 2; np++) {
                    mma_f16(acc[mt][2 * np],     a[mt], &b[np][0]);
                    mma_f16(acc[mt][2 * np + 1], a[mt], &b[np][2]);
                }
            }
        }
    }

    // store spectral result
    const int q4 = lid >> 2;
    const int r4 = lid & 3;
    #pragma unroll
    for (int mt = 0; mt < 4; mt++) {
        const int r  = wm * 64 + mt * 16 + q4;
        const int gm = m0 + r;
        #pragma unroll
        for (int nt = 0; nt < 4; nt++) {
            const int c = wn * 32 + nt * 8 + 2 * r4;
            if (gm < NV)
                *(float2*)&g_S[(size_t)gm * NJ + n0 + c] =
                    make_float2(acc[mt][nt][0], acc[mt][nt][1]);
            if (gm + 8 < NV)
                *(float2*)&g_S[(size_t)(gm + 8) * NJ + n0 + c] =
                    make_float2(acc[mt][nt][2], acc[mt][nt][3]);
        }
    }
}

// ---------------------------------------------------------------------------
// Kernel 4: inverse FFT over omega + bias + relu + k-sum
// ---------------------------------------------------------------------------
__global__ void epilogue(const float* __restrict__ bias, float* __restrict__ out)
{
    const int n = blockIdx.x;
    const int o = threadIdx.x;
    const float* S = g_S + (size_t)n * NJ;

    float C[8][2];
    #pragma unroll
    for (int gg = 0; gg < 8; gg++)
        #pragma unroll
        for (int k = 0; k < 2; k++)
            C[gg][k] = S[gg * 256 + k * OO + o];

    const float ct[8] = {1.f, 0.70710678f, 0.f, -0.70710678f,
                         -1.f, -0.70710678f, 0.f, 0.70710678f};
    const float st[8] = {0.f, 0.70710678f, 1.f, 0.70710678f,
                         0.f, -0.70710678f, -1.f, -0.70710678f};
    const float b0 = 40.f * __ldg(&bias[o]);
    const float b1 = 40.f * __ldg(&bias[OO + o]);

    #pragma unroll
    for (int rot = 0; rot < 8; rot++) {
        const float sgn = (rot & 1) ? -1.f : 1.f;
        float s0 = C[0][0] + sgn * C[7][0]
                 + C[1][0] * ct[rot]           - C[2][0] * st[rot]
                 + C[3][0] * ct[(2 * rot) & 7] - C[4][0] * st[(2 * rot) & 7]
                 + C[5][0] * ct[(3 * rot) & 7] - C[6][0] * st[(3 * rot) & 7];
        float s1 = C[0][1] + sgn * C[7][1]
                 + C[1][1] * ct[rot]           - C[2][1] * st[rot]
                 + C[3][1] * ct[(2 * rot) & 7] - C[4][1] * st[(2 * rot) & 7]
                 + C[5][1] * ct[(3 * rot) & 7] - C[6][1] * st[(3 * rot) & 7];
        out[(size_t)n * (NROT * OO) + rot * OO + o] =
            fmaxf(s0 + b0, 0.f) + fmaxf(s1 + b1, 0.f);
    }
}

// ---------------------------------------------------------------------------
extern "C" void kernel_launch(void* const* d_in, const int* in_sizes, int n_in,
                              void* d_out, int out_size)
{
    const float *ms = nullptr, *bary = nullptr, *W = nullptr,
                *bias = nullptr, *interp = nullptr;
    for (int i = 0; i < n_in; i++) {
        switch (in_sizes[i]) {
            case NV * FF:             ms     = (const float*)d_in[i]; break;
            case NV * RA * 3 * 2:     bary   = (const float*)d_in[i]; break;
            case RA * KK * OO * FF:   W      = (const float*)d_in[i]; break;
            case KK * OO:             bias   = (const float*)d_in[i]; break;
            case RA * RA:             interp = (const float*)d_in[i]; break;
            default: break;
        }
    }
    float* out = (float*)d_out;

    make_M<<<(RA * RA + 255) / 256, 256>>>(interp);
    gatherA<<<NV, 256>>>(ms, bary);
    buildB<<<5 * 256, FF>>>(W);

    cudaFuncSetAttribute(gemm_mma, cudaFuncAttributeMaxDynamicSharedMemorySize, DYNSMEM);
    dim3 gg(16, (NV + BM - 1) / BM);      // heavy column-groups first
    gemm_mma<<<gg, 256, DYNSMEM>>>();

    epilogue<<<NV, OO>>>(bias, out);
}

// round 12
// speedup vs baseline: 19.7083x; 1.3812x over previous
#include <cuda_runtime.h>
#include <cuda_fp16.h>
#include <cstdint>

// ---------------- problem constants ----------------
#define NV    6000
#define RR    5
#define AA    8
#define FF    128
#define KK    2
#define OO    128
#define RA    40
#define NROT  8
#define NP    55                  // spectral p-rows incl. u (8 comps*5 + 3 u*5)
#define KDIMA 7040                // NP*128 A' columns
#define NGRP  11                  // column groups, each 256 cols, K=640
#define NJ2   (NGRP*256)          // 2816 spectral output cols
#define KG    640                 // uniform per-group K

// ---------------- GEMM tiling ----------------
#define BM    128
#define BN    128
#define BK    64
#define ASTB  144
#define A_BYTES (BM*ASTB)
#define B_BYTES (BN*ASTB)
#define STG_BYTES (A_BYTES + B_BYTES)
#define NSTG  3
#define DYNSMEM (NSTG*STG_BYTES)  // 110592 -> 2 CTAs/SM

// ---------------- scratch ----------------
__device__ __half g_A [(size_t)NV * KDIMA];    // spectral A' (+u cols)  84.5 MB
__device__ __half g_B2[(size_t)NJ2 * KG];      // Karatsuba B            3.6 MB
__device__ float  g_S [(size_t)NV * NJ2];      // spectral GEMM result  67.6 MB
__device__ __half g_Mh[64 * 48];               // padded fold matrix (fp16)

// A-col offset per group: {om0, om4, om1:m1,m2,m3, om2:m1,m2,m3, om3:m1,m2,m3}
__device__ __constant__ int c_aoff[NGRP] =
    {0, 4480, 5120, 640, 1280, 5760, 1920, 2560, 6400, 3200, 3840};

// ---------------- PTX helpers ----------------
__device__ __forceinline__ uint32_t smem_u32(const void* p) {
    uint32_t a;
    asm("{ .reg .u64 t; cvta.to.shared.u64 t, %1; cvt.u32.u64 %0, t; }"
        : "=r"(a) : "l"(p));
    return a;
}
__device__ __forceinline__ void cpasync16(uint32_t saddr, const void* g, int srcsz) {
    asm volatile("cp.async.cg.shared.global [%0], [%1], 16, %2;"
                 :: "r"(saddr), "l"(g), "r"(srcsz) : "memory");
}
#define CP_COMMIT() asm volatile("cp.async.commit_group;" ::: "memory")
#define CP_WAIT1()  asm volatile("cp.async.wait_group 1;" ::: "memory")

__device__ __forceinline__ void ldsm_x4(uint32_t* r, uint32_t addr) {
    asm volatile("ldmatrix.sync.aligned.m8n8.x4.shared.b16 {%0,%1,%2,%3}, [%4];"
                 : "=r"(r[0]), "=r"(r[1]), "=r"(r[2]), "=r"(r[3]) : "r"(addr));
}
__device__ __forceinline__ void ldsm_x4_t(uint32_t* r, uint32_t addr) {
    asm volatile("ldmatrix.sync.aligned.m8n8.x4.trans.shared.b16 {%0,%1,%2,%3}, [%4];"
                 : "=r"(r[0]), "=r"(r[1]), "=r"(r[2]), "=r"(r[3]) : "r"(addr));
}
__device__ __forceinline__ void mma_f16(float* d, const uint32_t* a, const uint32_t* b) {
    asm volatile(
        "mma.sync.aligned.m16n8k16.row.col.f32.f16.f16.f32 "
        "{%0,%1,%2,%3}, {%4,%5,%6,%7}, {%8,%9}, {%0,%1,%2,%3};"
        : "+f"(d[0]), "+f"(d[1]), "+f"(d[2]), "+f"(d[3])
        : "r"(a[0]), "r"(a[1]), "r"(a[2]), "r"(a[3]), "r"(b[0]), "r"(b[1]));
}

// ---------------------------------------------------------------------------
// Kernel 0: padded fold matrix (fp16).  p<40: comp=p/5 (re/im DFT of interp);
// p in [40,55): u-rows = re+im.  Zeros elsewhere (64x48 pad).
// ---------------------------------------------------------------------------
__global__ void make_M(const float* __restrict__ interp)
{
    const int e = blockIdx.x * 256 + threadIdx.x;
    if (e >= 64 * 48) return;
    const int p = e / 48, q = e % 48;
    float acc = 0.f;
    if (p < NP && q < RA) {
        const int r = p % RR;
        #pragma unroll
        for (int b = 0; b < AA; b++) {
            float coef;
            if (p < RA) {
                const int comp = p / RR;
                if (comp == 0)      coef = 1.f;
                else if (comp == 7) coef = (b & 1) ? -1.f : 1.f;
                else {
                    const int m = (comp + 1) >> 1;
                    const float x = 0.25f * (float)(m * b);
                    coef = (comp & 1) ? cospif(x) : -sinpif(x);
                }
            } else {                       // u-rows: cos - sin
                const int om = (p - RA) / RR + 1;
                const float x = 0.25f * (float)(om * b);
                coef = cospif(x) - sinpif(x);
            }
            acc += coef * interp[r * (AA * RA) + b * RA + q];
        }
    }
    g_Mh[p * 48 + q] = __float2half_rn(acc);
}

// ---------------------------------------------------------------------------
// Kernel 1: gather + barycentric -> fp16 sig smem; HMMA fold A' = M * sig;
//           coalesced A' store. One block per vertex n.
// ---------------------------------------------------------------------------
__global__ void __launch_bounds__(256)
gatherA(const float* __restrict__ ms, const float* __restrict__ bary)
{
    __shared__ __half s_M  [64][56];   // stride 112B -> conflict-free ldsm
    __shared__ __half s_sig[48][136];  // stride 272B -> conflict-free trans-ldsm
    __shared__ __half s_out[64][136];  // fold result staging (16B-aligned rows)

    const int n    = blockIdx.x;
    const int tid  = threadIdx.x;
    const int wid  = tid >> 5;
    const int lane = tid & 31;

    // load M (pad cols 48..55 with zero)
    for (int i = tid; i < 64 * 56; i += 256) {
        const int r = i / 56, c = i % 56;
        s_M[r][c] = (c < 48) ? g_Mh[r * 48 + c] : __float2half_rn(0.f);
    }
    // zero sig pad rows 40..47
    for (int i = tid; i < 8 * 68; i += 256)
        *((uint32_t*)&s_sig[40 + i / 68][0] + (i % 68)) = 0u;

    // gather: warp per q-row
    #pragma unroll
    for (int it = 0; it < 5; it++) {
        const int q   = wid + 8 * it;
        const int row = n * RA + q;
        float bv = (lane < 6) ? bary[(size_t)row * 6 + lane] : 0.f;
        const int   i0 = (int)__shfl_sync(0xffffffffu, bv, 0);
        const float w0 =      __shfl_sync(0xffffffffu, bv, 1);
        const int   i1 = (int)__shfl_sync(0xffffffffu, bv, 2);
        const float w1 =      __shfl_sync(0xffffffffu, bv, 3);
        const int   i2 = (int)__shfl_sync(0xffffffffu, bv, 4);
        const float w2 =      __shfl_sync(0xffffffffu, bv, 5);

        const float4 a = __ldg((const float4*)(ms + (size_t)i0 * FF) + lane);
        const float4 b = __ldg((const float4*)(ms + (size_t)i1 * FF) + lane);
        const float4 c = __ldg((const float4*)(ms + (size_t)i2 * FF) + lane);
        const float v0 = w0 * a.x + w1 * b.x + w2 * c.x;
        const float v1 = w0 * a.y + w1 * b.y + w2 * c.y;
        const float v2 = w0 * a.z + w1 * b.z + w2 * c.z;
        const float v3 = w0 * a.w + w1 * b.w + w2 * c.w;
        __half2 h01 = __floats2half2_rn(v0, v1);
        __half2 h23 = __floats2half2_rn(v2, v3);
        *(__half2*)&s_sig[q][lane * 4]     = h01;
        *(__half2*)&s_sig[q][lane * 4 + 2] = h23;
    }
    __syncthreads();

    // HMMA fold: warp w handles f-chunk nc=w (16 cols), all 4 m-tiles.
    const uint32_t sMb = smem_u32(&s_M[0][0]);
    const uint32_t sSb = smem_u32(&s_sig[0][0]);
    const int grp = lane >> 3;
    const int wit = lane & 7;
    const int nc  = wid;

    uint32_t bfr[3][4];
    #pragma unroll
    for (int ks = 0; ks < 3; ks++)
        ldsm_x4_t(bfr[ks], sSb + (uint32_t)((ks * 16 + (grp & 1) * 8 + wit) * 272
                                            + (grp >> 1) * 16 + nc * 32));
    #pragma unroll
    for (int mt = 0; mt < 4; mt++) {
        float acc[2][4] = {{0.f,0.f,0.f,0.f},{0.f,0.f,0.f,0.f}};
        #pragma unroll
        for (int ks = 0; ks < 3; ks++) {
            uint32_t a[4];
            ldsm_x4(a, sMb + (uint32_t)((mt * 16 + (grp & 1) * 8 + wit) * 112
                                        + (grp >> 1) * 16 + ks * 32));
            mma_f16(acc[0], a, &bfr[ks][0]);
            mma_f16(acc[1], a, &bfr[ks][2]);
        }
        const int p  = mt * 16 + (lane >> 2);
        const int fb = nc * 16 + 2 * (lane & 3);
        *(__half2*)&s_out[p][fb]         = __floats2half2_rn(acc[0][0], acc[0][1]);
        *(__half2*)&s_out[p + 8][fb]     = __floats2half2_rn(acc[0][2], acc[0][3]);
        *(__half2*)&s_out[p][fb + 8]     = __floats2half2_rn(acc[1][0], acc[1][1]);
        *(__half2*)&s_out[p + 8][fb + 8] = __floats2half2_rn(acc[1][2], acc[1][3]);
    }
    __syncthreads();

    // coalesced A' store: 55 rows x 128 fp16
    for (int i = tid; i < NP * 16; i += 256) {
        const int r = i >> 4, c = i & 15;
        uint4 v = *(const uint4*)&s_out[r][c * 8];
        *(uint4*)(g_A + (size_t)n * KDIMA + r * FF + c * 8) = v;
    }
}

// ---------------------------------------------------------------------------
// Kernel 2: Karatsuba spectral B.  Block = om*256 + k*128 + o.
//   om0 -> group0 rows: 0.125*sum_b W;  om4 -> group1: 0.125*sum (-1)^b W
//   om=1..3, base=2+3(om-1):
//     m1 (base)  : 0.25*whi       (dotted with u = ar+ai)
//     m2 (base+1): 0.25*(whr-whi) (vs ar)
//     m3 (base+2): 0.25*(whr+whi) (vs ai)
// ---------------------------------------------------------------------------
__global__ void buildB(const float* __restrict__ W)
{
    const int bid = blockIdx.x;
    const int om  = bid >> 8;
    const int k   = (bid >> 7) & 1;
    const int o   = bid & 127;
    const int f   = threadIdx.x;
    const int ko  = k * OO + o;

    float w[RR][AA];
    #pragma unroll
    for (int r = 0; r < RR; r++)
        #pragma unroll
        for (int b = 0; b < AA; b++)
            w[r][b] = __ldg(&W[((((size_t)(r * AA + b)) * KK + k) * OO + o) * FF + f]);

    if (om == 0) {
        #pragma unroll
        for (int r = 0; r < RR; r++) {
            float s = 0.f;
            #pragma unroll
            for (int b = 0; b < AA; b++) s += w[r][b];
            g_B2[(size_t)(0 * 256 + ko) * KG + r * FF + f] = __float2half_rn(0.125f * s);
        }
    } else if (om == 4) {
        #pragma unroll
        for (int r = 0; r < RR; r++) {
            float s = 0.f;
            #pragma unroll
            for (int b = 0; b < AA; b++) s += ((b & 1) ? -w[r][b] : w[r][b]);
            g_B2[(size_t)(1 * 256 + ko) * KG + r * FF + f] = __float2half_rn(0.125f * s);
        }
    } else {
        const int base = 2 + 3 * (om - 1);
        #pragma unroll
        for (int r = 0; r < RR; r++) {
            float sr = 0.f, si = 0.f;
            #pragma unroll
            for (int b = 0; b < AA; b++) {
                const float x = 0.25f * (float)(om * b);
                sr = fmaf(cospif(x), w[r][b], sr);
                si = fmaf(-sinpif(x), w[r][b], si);
            }
            const float whr = 0.25f * sr, whi = 0.25f * si;
            g_B2[(size_t)((base    ) * 256 + ko) * KG + r * FF + f] = __float2half_rn(whi);
            g_B2[(size_t)((base + 1) * 256 + ko) * KG + r * FF + f] = __float2half_rn(whr - whi);
            g_B2[(size_t)((base + 2) * 256 + ko) * KG + r * FF + f] = __float2half_rn(whr + whi);
        }
    }
}

// ---------------------------------------------------------------------------
// Kernel 3: uniform block-diagonal GEMM.  cg = blockIdx.x: gr = cg>>1,
//   half = cg&1.  All groups K=640 (10 stages).  2 CTAs/SM.
// ---------------------------------------------------------------------------
__global__ void __launch_bounds__(256, 2)
gemm_mma()
{
    extern __shared__ char smem[];
    const uint32_t sbase = smem_u32(smem);

    const int tid = threadIdx.x;
    const int lid = tid & 31;
    const int wid = tid >> 5;
    const int wm  = wid >> 2;
    const int wn  = wid & 3;
    const int cg  = blockIdx.x;
    const int m0  = blockIdx.y * BM;
    const int gr  = cg >> 1;
    const int n0  = gr * 256 + (cg & 1) * 128;
    const int aoff = c_aoff[gr];
    const int ns   = KG / BK;            // 10

    const int grp = lid >> 3;
    const int wit = lid & 7;
    const uint32_t aoffs = (uint32_t)((wm * 64 + (grp & 1) * 8 + wit) * ASTB
                                      + (grp >> 1) * 16);
    const uint32_t boffs = (uint32_t)A_BYTES
                         + (uint32_t)((wn * 32 + (grp >> 1) * 8 + wit) * ASTB
                                      + (grp & 1) * 16);

    float acc[4][4][4];
    #pragma unroll
    for (int mt = 0; mt < 4; mt++)
        #pragma unroll
        for (int nt = 0; nt < 4; nt++)
            #pragma unroll
            for (int i = 0; i < 4; i++) acc[mt][nt][i] = 0.f;

    auto issue_stage = [&](int sp) {
        const int kk0 = sp * BK;
        const uint32_t sb = sbase + (uint32_t)(sp % NSTG) * STG_BYTES;
        #pragma unroll
        for (int i = 0; i < 4; i++) {
            const int id  = tid + i * 256;
            const int r   = id >> 3;
            const int c16 = id & 7;
            const int gm  = m0 + r;
            const bool v  = gm < NV;
            const __half* gp = g_A + (size_t)(v ? gm : 0) * KDIMA + aoff + kk0 + c16 * 8;
            cpasync16(sb + r * ASTB + c16 * 16, gp, v ? 16 : 0);
        }
        #pragma unroll
        for (int i = 0; i < 4; i++) {
            const int id  = tid + i * 256;
            const int r   = id >> 3;
            const int c16 = id & 7;
            const __half* gp = g_B2 + (size_t)(n0 + r) * KG + kk0 + c16 * 8;
            cpasync16(sb + A_BYTES + r * ASTB + c16 * 16, gp, 16);
        }
        CP_COMMIT();
    };

    issue_stage(0);
    issue_stage(1);

    for (int s = 0; s < ns; s++) {
        CP_WAIT1();
        __syncthreads();
        if (s + 2 < ns) issue_stage(s + 2); else CP_COMMIT();

        const uint32_t sb = sbase + (uint32_t)(s % NSTG) * STG_BYTES;
        #pragma unroll
        for (int ks = 0; ks < 4; ks++) {
            uint32_t a[4][4], b[2][4];
            #pragma unroll
            for (int mt = 0; mt < 4; mt++)
                ldsm_x4(a[mt], sb + aoffs + mt * (16 * ASTB) + ks * 32);
            #pragma unroll
            for (int np = 0; np < 2; np++)
                ldsm_x4(b[np], sb + boffs + np * (16 * ASTB) + ks * 32);
            #pragma unroll
            for (int mt = 0; mt < 4; mt++) {
                #pragma unroll
                for (int np = 0; np < 2; np++) {
                    mma_f16(acc[mt][2 * np],     a[mt], &b[np][0]);
                    mma_f16(acc[mt][2 * np + 1], a[mt], &b[np][2]);
                }
            }
        }
    }

    const int q4 = lid >> 2;
    const int r4 = lid & 3;
    #pragma unroll
    for (int mt = 0; mt < 4; mt++) {
        const int r  = wm * 64 + mt * 16 + q4;
        const int gm = m0 + r;
        #pragma unroll
        for (int nt = 0; nt < 4; nt++) {
            const int c = wn * 32 + nt * 8 + 2 * r4;
            if (gm < NV)
                *(float2*)&g_S[(size_t)gm * NJ2 + n0 + c] =
                    make_float2(acc[mt][nt][0], acc[mt][nt][1]);
            if (gm + 8 < NV)
                *(float2*)&g_S[(size_t)(gm + 8) * NJ2 + n0 + c] =
                    make_float2(acc[mt][nt][2], acc[mt][nt][3]);
        }
    }
}

// ---------------------------------------------------------------------------
// Kernel 4: Karatsuba combine + inverse FFT + bias + relu + k-sum
// ---------------------------------------------------------------------------
__global__ void epilogue(const float* __restrict__ bias, float* __restrict__ out)
{
    const int n = blockIdx.x;
    const int o = threadIdx.x;
    const float* S = g_S + (size_t)n * NJ2;

    float C0[2], C4[2], CR[3][2], CI[3][2];
    #pragma unroll
    for (int k = 0; k < 2; k++) {
        C0[k] = S[k * OO + o];
        C4[k] = S[256 + k * OO + o];
        #pragma unroll
        for (int om = 1; om <= 3; om++) {
            const int base = (2 + 3 * (om - 1)) * 256 + k * OO + o;
            const float m1 = S[base], m2 = S[base + 256], m3 = S[base + 512];
            CR[om - 1][k] = m1 + m2;
            CI[om - 1][k] = m1 - m3;
        }
    }

    const float ct[8] = {1.f, 0.70710678f, 0.f, -0.70710678f,
                         -1.f, -0.70710678f, 0.f, 0.70710678f};
    const float st[8] = {0.f, 0.70710678f, 1.f, 0.70710678f,
                         0.f, -0.70710678f, -1.f, -0.70710678f};
    const float b0 = 40.f * __ldg(&bias[o]);
    const float b1 = 40.f * __ldg(&bias[OO + o]);

    #pragma unroll
    for (int rot = 0; rot < 8; rot++) {
        const float sgn = (rot & 1) ? -1.f : 1.f;
        float s0 = C0[0] + sgn * C4[0];
        float s1 = C0[1] + sgn * C4[1];
        #pragma unroll
        for (int om = 1; om <= 3; om++) {
            const int ph = (om * rot) & 7;
            s0 += CR[om - 1][0] * ct[ph] - CI[om - 1][0] * st[ph];
            s1 += CR[om - 1][1] * ct[ph] - CI[om - 1][1] * st[ph];
        }
        out[(size_t)n * (NROT * OO) + rot * OO + o] =
            fmaxf(s0 + b0, 0.f) + fmaxf(s1 + b1, 0.f);
    }
}

// ---------------------------------------------------------------------------
extern "C" void kernel_launch(void* const* d_in, const int* in_sizes, int n_in,
                              void* d_out, int out_size)
{
    const float *ms = nullptr, *bary = nullptr, *W = nullptr,
                *bias = nullptr, *interp = nullptr;
    for (int i = 0; i < n_in; i++) {
        switch (in_sizes[i]) {
            case NV * FF:             ms     = (const float*)d_in[i]; break;
            case NV * RA * 3 * 2:     bary   = (const float*)d_in[i]; break;
            case RA * KK * OO * FF:   W      = (const float*)d_in[i]; break;
            case KK * OO:             bias   = (const float*)d_in[i]; break;
            case RA * RA:             interp = (const float*)d_in[i]; break;
            default: break;
        }
    }
    float* out = (float*)d_out;

    make_M<<<(64 * 48 + 255) / 256, 256>>>(interp);
    gatherA<<<NV, 256>>>(ms, bary);
    buildB<<<5 * 256, FF>>>(W);

    cudaFuncSetAttribute(gemm_mma, cudaFuncAttributeMaxDynamicSharedMemorySize, DYNSMEM);
    dim3 gg(2 * NGRP, (NV + BM - 1) / BM);
    gemm_mma<<<gg, 256, DYNSMEM>>>();

    epilogue<<<NV, OO>>>(bias, out);
}